// round 6
// baseline (speedup 1.0000x reference)
#include <cuda_runtime.h>
#include <cstdint>

// GRU-GNN fused kernel for GB300 (sm_103a), v2.
//   red[dst[e]] = h[src[e]]  (exactly one incoming edge per node)
//   gi = x @ w_ih^T + b_ih ; gh = red @ w_hh^T + b_hh
//   r=sig(i_r+h_r); z=sig(i_z+h_z); n=tanh(i_n + r*h_n); out=(1-z)n + z*red
//
// v2 vs v1 (3370us, L1=87.8% crossbar-bound): 4-row x 2-col x 6-gate register
// blocking with a kz(2) k-split across lane groups -> 96 FFMA2 per 20 LDS.128
// per 4-k step (was 48:16). kz lanes make weight loads 16-distinct (2 crossbar
// cyc vs 4). Split-row layout (+68 floats for k>=64) keeps all loads
// conflict-free. kz partners combine via 1 shfl per accumulator pair.

#define MTILE 64          // edges (rows) per tile
#define CTILE 16          // output columns per tile (x6 gate blocks)
#define SP    132         // row stride in floats (split layout: [0,64)+[68,132))
#define KO    68          // float offset of the k>=64 half within a row
#define NTHREADS 256
#define GRID 152

#define WS_FLOATS (6 * CTILE * SP)   // 12672
#define XS_FLOATS (2 * MTILE * SP)   // 16896 per double-buffered array
#define SMEM_BYTES ((WS_FLOATS + 2 * XS_FLOATS) * 4 + 6 * MTILE * 4)

__device__ __forceinline__ void fma2(unsigned long long& a,
                                     unsigned long long b,
                                     unsigned long long c) {
    // packed f32x2 FMA: a.lo += b.lo*c.lo ; a.hi += b.hi*c.hi  (SASS FFMA2)
    asm("fma.rn.f32x2 %0, %1, %2, %0;" : "+l"(a) : "l"(b), "l"(c));
}

__device__ __forceinline__ float sum2(unsigned long long v) {
    float lo = __uint_as_float((unsigned)(v & 0xffffffffull));
    float hi = __uint_as_float((unsigned)(v >> 32));
    return lo + hi;
}

__device__ __forceinline__ float sigmoid_f(float t) {
    return __fdividef(1.0f, 1.0f + __expf(-t));
}

__device__ __forceinline__ void cp16(void* s, const void* g) {
    unsigned sa = (unsigned)__cvta_generic_to_shared(s);
    asm volatile("cp.async.cg.shared.global [%0], [%1], 16;" :: "r"(sa), "l"(g));
}
#define CP_COMMIT() asm volatile("cp.async.commit_group;")
#define CP_WAIT0()  asm volatile("cp.async.wait_group 0;")

// split-row float offset for float4 chunk kq (0..31): [0,64) then [68,132)
__device__ __forceinline__ int fo4(int kq) { return 4 * kq + ((kq >= 16) ? 4 : 0); }

// cp.async one (x, red) row tile: 64 rows x 512B x 2 arrays, split-row layout
__device__ __forceinline__ void issue_tile(float* XS, float* RS,
                                           const int* IDXN, const int* IDXS,
                                           const float* __restrict__ x,
                                           const float* __restrict__ h,
                                           int buf, int slot, int t) {
#pragma unroll
    for (int j = 0; j < 8; j++) {
        int f   = t + NTHREADS * j;      // 0..2047
        int row = f >> 5;                // 0..63
        int kq  = f & 31;                // float4 index along k
        int fo  = fo4(kq);
        int node = IDXN[slot * MTILE + row];
        int s    = IDXS[slot * MTILE + row];
        cp16(XS + (buf * MTILE + row) * SP + fo, x + (size_t)node * 128 + 4 * kq);
        cp16(RS + (buf * MTILE + row) * SP + fo, h + (size_t)s    * 128 + 4 * kq);
    }
}

__global__ void __launch_bounds__(NTHREADS, 1)
gru_gnn_v2_kernel(const float* __restrict__ x, const float* __restrict__ h,
                  const float* __restrict__ w_ih, const float* __restrict__ w_hh,
                  const float* __restrict__ b_ih, const float* __restrict__ b_hh,
                  const int* __restrict__ src, const int* __restrict__ dst,
                  float* __restrict__ out, int N, int num_mt, int total)
{
    extern __shared__ __align__(16) char smem_raw[];
    float* WS = (float*)smem_raw;            // weights [6][CTILE][SP], split rows
    float* XS = WS + WS_FLOATS;              // x tiles  [2][MTILE][SP]
    float* RS = XS + XS_FLOATS;              // red tiles[2][MTILE][SP]
    int* IDXN = (int*)(RS + XS_FLOATS);      // [3][MTILE] output node per row
    int* IDXS = IDXN + 3 * MTILE;            // [3][MTILE] gather src per row

    const int t  = threadIdx.x;
    const int tx = t & 7;          // column within tile: cg = c0 + tx + 8*kz
    const int kz = (t >> 3) & 1;   // k-half: [0,64) or [64,128)
    const int ty = t >> 4;         // 0..15 -> rows 4*ty .. 4*ty+3
    const int G  = gridDim.x;

    int it0 = blockIdx.x;
    if (it0 >= total) return;

    // ---------------- prologue ----------------
    {
        int mt = it0 % num_mt;
        if (t < MTILE) {
            int e = mt * MTILE + t; if (e >= N) e = N - 1;
            IDXN[t] = dst[e];
            IDXS[t] = src[e];
        }
    }
    __syncthreads();
    issue_tile(XS, RS, IDXN, IDXS, x, h, /*buf=*/0, /*slot=*/0, t);
    CP_COMMIT();
    if (it0 + G < total) {
        int mt = (it0 + G) % num_mt;
        if (t < MTILE) {
            int e = mt * MTILE + t; if (e >= N) e = N - 1;
            IDXN[MTILE + t] = dst[e];
            IDXS[MTILE + t] = src[e];
        }
    }

    int cur_ct = -1;
    float bi0 = 0.f, bi1 = 0.f, bi2 = 0.f, bh0 = 0.f, bh1 = 0.f, bh2 = 0.f;

    // ---------------- main loop over work items (ct-major) ----------------
    for (int n = 0;; n++) {
        int it = it0 + n * G;
        if (it >= total) break;
        int buf  = n & 1;
        int slot = n % 3;
        int ct = it / num_mt;            // column tile (changes rarely)

        CP_WAIT0();                      // this tile's x/red copies retired
        __syncthreads();                 // ...visible to all; prior iter done

        bool wload = (ct != cur_ct);
        if (wload) {
            int c0 = ct * CTILE;
#pragma unroll
            for (int i = 0; i < 12; i++) {
                int f = t + NTHREADS * i;        // 3072 float4s = 6*16*32
                int rowf = f >> 5, kq = f & 31;
                int g = rowf >> 4, c = rowf & 15;
                const float* base = (g < 3) ? w_ih : w_hh;
                int g3 = (g < 3) ? g : g - 3;
                float4 v = *(const float4*)(base + ((size_t)(g3 * 128 + c0 + c)) * 128 + 4 * kq);
                *(float4*)(WS + (g * CTILE + c) * SP + fo4(kq)) = v;
            }
            int cg = c0 + tx + 8 * kz;
            bi0 = b_ih[cg];       bh0 = b_hh[cg];
            bi1 = b_ih[cg + 128]; bh1 = b_hh[cg + 128];
            bi2 = b_ih[cg + 256]; bh2 = b_hh[cg + 256];
            cur_ct = ct;
        }

        // prefetch next tile into the other buffer (overlaps compute)
        if (it + G < total) {
            issue_tile(XS, RS, IDXN, IDXS, x, h, buf ^ 1, (n + 1) % 3, t);
            CP_COMMIT();
        }
        // indices two tiles ahead (slot (n+2)%3: not read until next iter)
        if (it + 2 * G < total) {
            int mt2 = (it + 2 * G) % num_mt;
            int sl2 = (n + 2) % 3;
            if (t < MTILE) {
                int e = mt2 * MTILE + t; if (e >= N) e = N - 1;
                IDXN[sl2 * MTILE + t] = dst[e];
                IDXS[sl2 * MTILE + t] = src[e];
            }
        }
        if (wload) __syncthreads();      // weights visible before compute

        // ---------- compute: 4 rows x 2 cols x 6 gates over this kz half ----------
        unsigned long long acc[4][2][6];
#pragma unroll
        for (int r = 0; r < 4; r++)
#pragma unroll
            for (int ci = 0; ci < 2; ci++)
#pragma unroll
                for (int g = 0; g < 6; g++) acc[r][ci][g] = 0ull;

        const float* xb = XS + (buf * MTILE + 4 * ty) * SP + kz * KO;
        const float* rb = RS + (buf * MTILE + 4 * ty) * SP + kz * KO;
        const float* wb = WS + kz * KO;

#pragma unroll 4
        for (int k = 0; k < 64; k += 4) {
            ulonglong2 xv[4], rv[4];
#pragma unroll
            for (int r = 0; r < 4; r++) {
                xv[r] = *(const ulonglong2*)(xb + r * SP + k);
                rv[r] = *(const ulonglong2*)(rb + r * SP + k);
            }
#pragma unroll
            for (int g = 0; g < 6; g++) {
#pragma unroll
                for (int ci = 0; ci < 2; ci++) {
                    ulonglong2 wv = *(const ulonglong2*)(
                        wb + (g * CTILE + tx + 8 * ci) * SP + k);
#pragma unroll
                    for (int r = 0; r < 4; r++) {
                        fma2(acc[r][ci][g], wv.x, (g < 3) ? xv[r].x : rv[r].x);
                        fma2(acc[r][ci][g], wv.y, (g < 3) ? xv[r].y : rv[r].y);
                    }
                }
            }
        }

        // ---------- combine kz halves + GRU epilogue (1 col per thread) ----------
        int c0 = ct * CTILE;
        int cg = c0 + tx + 8 * kz;
        int co = cg + ((cg >= 64) ? 4 : 0);   // split-row offset of element cg
#pragma unroll
        for (int r = 0; r < 4; r++) {
            float s[6];
#pragma unroll
            for (int g = 0; g < 6; g++) {
                float skeep  = sum2(acc[r][kz ? 1 : 0][g]);   // my half, my col
                float ssend  = sum2(acc[r][kz ? 0 : 1][g]);   // my half, partner col
                float recv = __shfl_xor_sync(0xffffffffu, ssend, 8);
                s[g] = skeep + recv;                          // full-k sum for col cg
            }
            int row  = 4 * ty + r;
            int node = IDXN[slot * MTILE + row];
            float gr = s[0] + bi0, gz = s[1] + bi1, gn = s[2] + bi2;
            float hr = s[3] + bh0, hz = s[4] + bh1, hn = s[5] + bh2;
            float rg = sigmoid_f(gr + hr);
            float zg = sigmoid_f(gz + hz);
            float ng = tanhf(gn + rg * hn);
            float red = RS[(buf * MTILE + row) * SP + co];
            out[(size_t)node * 128 + cg] = (1.0f - zg) * ng + zg * red;
        }
    }
}

extern "C" void kernel_launch(void* const* d_in, const int* in_sizes, int n_in,
                              void* d_out, int out_size) {
    const float* x    = (const float*)d_in[0];
    const float* h    = (const float*)d_in[1];
    const float* w_ih = (const float*)d_in[2];
    const float* w_hh = (const float*)d_in[3];
    const float* b_ih = (const float*)d_in[4];
    const float* b_hh = (const float*)d_in[5];
    const int*   src  = (const int*)d_in[6];
    const int*   dst  = (const int*)d_in[7];
    float* out = (float*)d_out;

    int N = in_sizes[6];                 // #edges == #nodes
    int num_mt = (N + MTILE - 1) / MTILE;
    int total  = (128 / CTILE) * num_mt; // 8 column tiles

    cudaFuncSetAttribute(gru_gnn_v2_kernel,
                         cudaFuncAttributeMaxDynamicSharedMemorySize, SMEM_BYTES);

    int grid = GRID < total ? GRID : total;
    gru_gnn_v2_kernel<<<grid, NTHREADS, SMEM_BYTES>>>(
        x, h, w_ih, w_hh, b_ih, b_hh, src, dst, out, N, num_mt, total);
}